// round 1
// baseline (speedup 1.0000x reference)
#include <cuda_runtime.h>

// Dice score: input (B=4, C=5, 128^3) fp32 logits, target (4, 128^3) int class ids.
// pred = argmax over C; per-batch per-class counts of pred / target / intersection
// (classes 1..4 only); dice = (2I+eps)/(P+T+eps); mean over 16 values -> out[0].

#define NB 4
#define NC 5
#define NPOS (1 << 21)                  // 128^3
#define TPB 256
#define POS_PER_THREAD 16
#define POS_PER_BLOCK (TPB * POS_PER_THREAD)      // 4096 (divides NPOS -> block never straddles batches)
#define NBLOCKS ((NB * NPOS) / POS_PER_BLOCK)     // 2048

// scratch: [b][0=pred,1=tgt,2=inter][c]
__device__ int g_cnt[NB][3][NC];
__device__ int g_is64;

// Zero counters + detect target dtype (int64 vs int32).
// If the buffer is int32, interpreting pairs as int64 yields values >= 2^32
// whenever the odd word is a nonzero class id; P(all 256 odd words == 0) ~ (1/5)^256.
__global__ void k_init(const long long* __restrict__ tgt) {
    int t = threadIdx.x;
    if (t < NB * 3 * NC) ((int*)g_cnt)[t] = 0;
    if (t == 0) {
        int ok = 1;
        for (int i = 0; i < 256; i++) {
            long long v = tgt[i];
            if (v < 0 || v > (NC - 1)) { ok = 0; break; }
        }
        g_is64 = ok;
    }
}

__global__ void __launch_bounds__(TPB) k_count(const float* __restrict__ inp,
                                               const void* __restrict__ tgt) {
    __shared__ int s_cnt[12];            // [kind 0..2][class-1 0..3]
    const int tid  = threadIdx.x;
    const int lane = tid & 31;
    if (tid < 12) s_cnt[tid] = 0;
    __syncthreads();

    const long blockbase = (long)blockIdx.x * POS_PER_BLOCK;
    const int  b   = (int)(blockbase >> 21);
    const long n0  = (blockbase & (NPOS - 1)) + (long)tid * 4;
    const float* base = inp + (long)b * NC * NPOS + n0;
    const int is64 = g_is64;

    int pcnt[4] = {0, 0, 0, 0};
    int tcnt[4] = {0, 0, 0, 0};
    int icnt[4] = {0, 0, 0, 0};

    #pragma unroll
    for (int j = 0; j < POS_PER_THREAD / 4; j++) {
        // ---- targets (4 positions) ----
        const long gq = (blockbase >> 2) + (long)j * TPB + tid;  // float4-granule index
        int tv[4];
        if (is64) {
            longlong4 t4 = ((const longlong4*)tgt)[gq];
            tv[0] = (int)t4.x; tv[1] = (int)t4.y; tv[2] = (int)t4.z; tv[3] = (int)t4.w;
        } else {
            int4 t4 = ((const int4*)tgt)[gq];
            tv[0] = t4.x; tv[1] = t4.y; tv[2] = t4.z; tv[3] = t4.w;
        }

        // ---- logits: 5 classes x float4 ----
        float va[NC][4];
        #pragma unroll
        for (int c = 0; c < NC; c++) {
            float4 v = *(const float4*)(base + (long)c * NPOS + (long)j * (TPB * 4));
            va[c][0] = v.x; va[c][1] = v.y; va[c][2] = v.z; va[c][3] = v.w;
        }

        // ---- per position: vmax, flags, warp-ballot histogram ----
        #pragma unroll
        for (int k = 0; k < 4; k++) {
            const float f0 = va[0][k], f1 = va[1][k], f2 = va[2][k],
                        f3 = va[3][k], f4 = va[4][k];
            const float m = fmaxf(fmaxf(fmaxf(f0, f1), fmaxf(f2, f3)), f4);

            const unsigned pm1 = __ballot_sync(0xffffffffu, f1 == m);
            const unsigned pm2 = __ballot_sync(0xffffffffu, f2 == m);
            const unsigned pm3 = __ballot_sync(0xffffffffu, f3 == m);
            const unsigned pm4 = __ballot_sync(0xffffffffu, f4 == m);

            const int t = tv[k];
            const unsigned tm1 = __ballot_sync(0xffffffffu, t == 1);
            const unsigned tm2 = __ballot_sync(0xffffffffu, t == 2);
            const unsigned tm3 = __ballot_sync(0xffffffffu, t == 3);
            const unsigned tm4 = __ballot_sync(0xffffffffu, t == 4);

            pcnt[0] += __popc(pm1); pcnt[1] += __popc(pm2);
            pcnt[2] += __popc(pm3); pcnt[3] += __popc(pm4);
            tcnt[0] += __popc(tm1); tcnt[1] += __popc(tm2);
            tcnt[2] += __popc(tm3); tcnt[3] += __popc(tm4);
            icnt[0] += __popc(pm1 & tm1); icnt[1] += __popc(pm2 & tm2);
            icnt[2] += __popc(pm3 & tm3); icnt[3] += __popc(pm4 & tm4);
        }
    }

    // warp -> block (shared) reduction: all lanes hold identical ballot sums
    if (lane == 0) {
        #pragma unroll
        for (int c = 0; c < 4; c++) {
            atomicAdd(&s_cnt[0 * 4 + c], pcnt[c]);
            atomicAdd(&s_cnt[1 * 4 + c], tcnt[c]);
            atomicAdd(&s_cnt[2 * 4 + c], icnt[c]);
        }
    }
    __syncthreads();

    // block -> global
    if (tid < 12) {
        const int kind = tid >> 2;
        const int c    = (tid & 3) + 1;
        atomicAdd(&g_cnt[b][kind][c], s_cnt[tid]);
    }
}

__global__ void k_final(float* __restrict__ out) {
    if (threadIdx.x == 0) {
        float s = 0.0f;
        #pragma unroll
        for (int b = 0; b < NB; b++) {
            #pragma unroll
            for (int c = 1; c < NC; c++) {
                const float I = (float)g_cnt[b][2][c];
                const float U = (float)(g_cnt[b][0][c] + g_cnt[b][1][c]);
                s += (2.0f * I + 1e-5f) / (U + 1e-5f);
            }
        }
        out[0] = s * (1.0f / (NB * (NC - 1)));
    }
}

extern "C" void kernel_launch(void* const* d_in, const int* in_sizes, int n_in,
                              void* d_out, int out_size) {
    const float* inp = (const float*)d_in[0];
    const void*  tgt = d_in[1];
    float* out = (float*)d_out;
    (void)in_sizes; (void)n_in; (void)out_size;

    k_init<<<1, 64>>>((const long long*)tgt);
    k_count<<<NBLOCKS, TPB>>>(inp, tgt);
    k_final<<<1, 1>>>(out);
}